// round 2
// baseline (speedup 1.0000x reference)
#include <cuda_runtime.h>

// Problem constants
#define NN   50000
#define EE   800000
#define ROW  160      // Text row stride in floats: [T 0..127 | xb 128..143 | rootx 144..159]

// ---------------- scratch (static device memory; no runtime allocation) ----------------
__device__ float g_Text[(size_t)NN * ROW];  // 32 MB, fits L2
__device__ float g_h[NN * 16];
__device__ float g_agg0[NN * 16];
__device__ float g_agg1[NN * 16];
__device__ float g_cnt[NN];
__device__ int   g_is64;   // 1 if edge_index is int64, 0 if int32

// ---------------- helpers ----------------
__device__ __forceinline__ float4 f4fma(float s, float4 a, float4 b) {
    b.x = fmaf(s, a.x, b.x);
    b.y = fmaf(s, a.y, b.y);
    b.z = fmaf(s, a.z, b.z);
    b.w = fmaf(s, a.w, b.w);
    return b;
}

// vectorized no-return atomic add (sm_90+, PTX ISA 8.1)
__device__ __forceinline__ void red4(float* p, float4 v) {
    asm volatile("red.global.add.v4.f32 [%0], {%1, %2, %3, %4};"
                 :: "l"(p), "f"(v.x), "f"(v.y), "f"(v.z), "f"(v.w)
                 : "memory");
}

// ---------------- kernels ----------------

// Probe edge_index dtype: if genuinely int64, every 8-byte word is a valid
// node id (< NN). If it's int32 data read as int64, upper words carry the
// next index and the value explodes.
__global__ void detect_kernel(const void* ei) {
    const unsigned long long* p = (const unsigned long long*)ei;
    int ok = 1;
    for (int i = 0; i < 64; i++) {
        if (p[i] >= (unsigned long long)NN) { ok = 0; break; }
    }
    g_is64 = ok;
}

__global__ void zero_kernel() {
    int idx = blockIdx.x * blockDim.x + threadIdx.x;
    int stride = gridDim.x * blockDim.x;
    for (int i = idx; i < NN * 16; i += stride) {
        g_agg0[i] = 0.f;
        g_agg1[i] = 0.f;
    }
    for (int i = idx; i < NN; i += stride) g_cnt[i] = 0.f;
}

// Build Text[n, 0..159]:
//   j in [0,128):   T[n,d,o]    = sum_i in[n,i] * nn_w[d*256 + i*16 + o]   (d=j>>4, o=j&15)
//   j in [128,144): xb[n,o]     = sum_i in[n,i] * nn_b[i*16 + o]
//   j in [144,160): rootx[n,o]  = sum_i in[n,i] * root[i*16 + o] + bias[o]
__global__ void node_prep_kernel(const float* __restrict__ xin,   // nullptr -> use g_h
                                 const float* __restrict__ nw,
                                 const float* __restrict__ nb,
                                 const float* __restrict__ rt,
                                 const float* __restrict__ bs) {
    __shared__ float Wc[16 * ROW];
    __shared__ float Bc[ROW];
    const float* in = (xin != nullptr) ? xin : g_h;

    for (int t = threadIdx.x; t < 16 * ROW; t += blockDim.x) {
        int i = t / ROW, j = t % ROW;
        float w;
        if (j < 128) {
            int d = j >> 4, o = j & 15;
            w = nw[d * 256 + i * 16 + o];
        } else if (j < 144) {
            int o = j - 128;
            w = nb[i * 16 + o];
        } else {
            int o = j - 144;
            w = rt[i * 16 + o];
        }
        Wc[t] = w;
    }
    for (int t = threadIdx.x; t < ROW; t += blockDim.x)
        Bc[t] = (t >= 144) ? bs[t - 144] : 0.f;
    __syncthreads();

    const int total = NN * (ROW / 4);  // one thread per float4 of output
    for (int g = blockIdx.x * blockDim.x + threadIdx.x; g < total;
         g += gridDim.x * blockDim.x) {
        int n = g / (ROW / 4);
        int j4 = g % (ROW / 4);
        const float4* xr = (const float4*)(in + (size_t)n * 16);
        float4 x0 = xr[0], x1 = xr[1], x2 = xr[2], x3 = xr[3];
        float xv[16] = {x0.x, x0.y, x0.z, x0.w, x1.x, x1.y, x1.z, x1.w,
                        x2.x, x2.y, x2.z, x2.w, x3.x, x3.y, x3.z, x3.w};
        float4 acc = *(const float4*)&Bc[j4 * 4];
#pragma unroll
        for (int i = 0; i < 16; i++) {
            float4 w = *(const float4*)&Wc[i * ROW + j4 * 4];
            acc = f4fma(xv[i], w, acc);
        }
        *(float4*)&g_Text[(size_t)n * ROW + j4 * 4] = acc;
    }
}

// One thread per edge:
//   msg[o] = xb[src,o] + sum_d ea[e,d] * T[src,d,o];  red into agg[dst]
__global__ void edge_kernel(const void* __restrict__ ei_raw,
                            const float* __restrict__ ea,
                            int layer, int do_cnt) {
    int e = blockIdx.x * blockDim.x + threadIdx.x;
    if (e >= EE) return;

    int src, dst;
    if (g_is64) {
        const long long* ei = (const long long*)ei_raw;
        src = (int)ei[e];
        dst = (int)ei[EE + e];
    } else {
        const int* ei = (const int*)ei_raw;
        src = ei[e];
        dst = ei[EE + e];
    }
    // Defensive: a bad index should produce a visible correctness error, not an IMA.
    if ((unsigned)src >= NN || (unsigned)dst >= NN) return;

    const float4* eap = (const float4*)(ea + (size_t)e * 8);
    float4 a0 = eap[0], a1 = eap[1];
    float w[8] = {a0.x, a0.y, a0.z, a0.w, a1.x, a1.y, a1.z, a1.w};

    const float4* Tr = (const float4*)(g_Text + (size_t)src * ROW);
    // init with xb (cols 128..143 = float4 indices 32..35)
    float4 acc0 = Tr[32], acc1 = Tr[33], acc2 = Tr[34], acc3 = Tr[35];
#pragma unroll
    for (int d = 0; d < 8; d++) {
        float wd = w[d];
        acc0 = f4fma(wd, Tr[d * 4 + 0], acc0);
        acc1 = f4fma(wd, Tr[d * 4 + 1], acc1);
        acc2 = f4fma(wd, Tr[d * 4 + 2], acc2);
        acc3 = f4fma(wd, Tr[d * 4 + 3], acc3);
    }

    float* dstp = (layer ? g_agg1 : g_agg0) + (size_t)dst * 16;
    red4(dstp + 0, acc0);
    red4(dstp + 4, acc1);
    red4(dstp + 8, acc2);
    red4(dstp + 12, acc3);
    if (do_cnt) atomicAdd(&g_cnt[dst], 1.0f);
}

// h[n,o] = relu(agg0[n,o]/max(cnt,1) + rootx0[n,o])
__global__ void relu_h_kernel() {
    int idx = blockIdx.x * blockDim.x + threadIdx.x;
    if (idx >= NN * 16) return;
    int n = idx >> 4, o = idx & 15;
    float c = fmaxf(g_cnt[n], 1.f);
    float v = g_agg0[idx] / c + g_Text[(size_t)n * ROW + 144 + o];
    g_h[idx] = fmaxf(v, 0.f);
}

// out[n] = sum_o relu(agg1[n,o]/max(cnt,1) + rootx1[n,o]) * head_w[o] + head_b
__global__ void head_kernel(const float* __restrict__ hw,
                            const float* __restrict__ hb,
                            float* __restrict__ out) {
    int n = blockIdx.x * blockDim.x + threadIdx.x;
    if (n >= NN) return;
    float inv = 1.f / fmaxf(g_cnt[n], 1.f);
    const float* ag = g_agg1 + (size_t)n * 16;
    const float* rx = g_Text + (size_t)n * ROW + 144;
    float s = hb[0];
#pragma unroll
    for (int o = 0; o < 16; o++) {
        float v = fmaxf(fmaf(ag[o], inv, rx[o]), 0.f);
        s = fmaf(v, hw[o], s);
    }
    out[n] = s;
}

// ---------------- launch ----------------
extern "C" void kernel_launch(void* const* d_in, const int* in_sizes, int n_in,
                              void* d_out, int out_size) {
    const float* x     = (const float*)d_in[0];
    const void*  ei    = d_in[1];
    const float* ea    = (const float*)d_in[2];
    const float* nn_w0 = (const float*)d_in[3];
    const float* nn_b0 = (const float*)d_in[4];
    const float* root0 = (const float*)d_in[5];
    const float* bias0 = (const float*)d_in[6];
    const float* nn_w1 = (const float*)d_in[7];
    const float* nn_b1 = (const float*)d_in[8];
    const float* root1 = (const float*)d_in[9];
    const float* bias1 = (const float*)d_in[10];
    const float* headw = (const float*)d_in[11];
    const float* headb = (const float*)d_in[12];
    float* out = (float*)d_out;

    const int TB = 256;
    detect_kernel<<<1, 1>>>(ei);
    zero_kernel<<<1024, TB>>>();
    node_prep_kernel<<<1184, TB>>>(x, nn_w0, nn_b0, root0, bias0);
    edge_kernel<<<(EE + TB - 1) / TB, TB>>>(ei, ea, /*layer=*/0, /*do_cnt=*/1);
    relu_h_kernel<<<(NN * 16 + TB - 1) / TB, TB>>>();
    node_prep_kernel<<<1184, TB>>>(nullptr, nn_w1, nn_b1, root1, bias1);
    edge_kernel<<<(EE + TB - 1) / TB, TB>>>(ei, ea, /*layer=*/1, /*do_cnt=*/0);
    head_kernel<<<(NN + TB - 1) / TB, TB>>>(headw, headb, out);
}

// round 5
// speedup vs baseline: 2.0238x; 2.0238x over previous
#include <cuda_runtime.h>

// Problem constants
#define NN   50000
#define EE   800000
#define ROW  160      // Text row stride in floats: [T 0..127 | xb 128..143 | rootx 144..159]
                      // 640 B/row -> 128B-line aligned; each 64B d-chunk sits in one line.

// ---------------- scratch (static device memory; no runtime allocation) ----------------
__device__ float g_Text[(size_t)NN * ROW];  // 32 MB, fits L2
__device__ float g_h[NN * 16];
__device__ float g_agg0[NN * 16];
__device__ float g_agg1[NN * 16];
__device__ float g_cnt[NN];
__device__ int   g_is64;   // 1 if edge_index is int64, 0 if int32

// ---------------- helpers ----------------
__device__ __forceinline__ float4 f4fma(float s, float4 a, float4 b) {
    b.x = fmaf(s, a.x, b.x);
    b.y = fmaf(s, a.y, b.y);
    b.z = fmaf(s, a.z, b.z);
    b.w = fmaf(s, a.w, b.w);
    return b;
}

// vectorized no-return atomic add (sm_90+, PTX ISA 8.1)
__device__ __forceinline__ void red4(float* p, float4 v) {
    asm volatile("red.global.add.v4.f32 [%0], {%1, %2, %3, %4};"
                 :: "l"(p), "f"(v.x), "f"(v.y), "f"(v.z), "f"(v.w)
                 : "memory");
}

// ---------------- kernels ----------------

// Probe edge_index dtype: int64 vs JAX-x64-disabled int32.
__global__ void detect_kernel(const void* ei) {
    const unsigned long long* p = (const unsigned long long*)ei;
    int ok = 1;
    for (int i = 0; i < 64; i++) {
        if (p[i] >= (unsigned long long)NN) { ok = 0; break; }
    }
    g_is64 = ok;
}

__global__ void zero_kernel() {
    int idx = blockIdx.x * blockDim.x + threadIdx.x;
    int stride = gridDim.x * blockDim.x;
    for (int i = idx; i < NN * 16; i += stride) {
        g_agg0[i] = 0.f;
        g_agg1[i] = 0.f;
    }
    for (int i = idx; i < NN; i += stride) g_cnt[i] = 0.f;
}

// Build Text[n, 0..159]:
//   j in [0,128):   T[n,d,o]    = sum_i in[n,i] * nn_w[d*256 + i*16 + o]   (d=j>>4, o=j&15)
//   j in [128,144): xb[n,o]     = sum_i in[n,i] * nn_b[i*16 + o]
//   j in [144,160): rootx[n,o]  = sum_i in[n,i] * root[i*16 + o] + bias[o]
__global__ void node_prep_kernel(const float* __restrict__ xin,   // nullptr -> use g_h
                                 const float* __restrict__ nw,
                                 const float* __restrict__ nb,
                                 const float* __restrict__ rt,
                                 const float* __restrict__ bs) {
    __shared__ float Wc[16 * ROW];
    __shared__ float Bc[ROW];
    const float* in = (xin != nullptr) ? xin : g_h;

    for (int t = threadIdx.x; t < 16 * ROW; t += blockDim.x) {
        int i = t / ROW, j = t % ROW;
        float w;
        if (j < 128) {
            int d = j >> 4, o = j & 15;
            w = nw[d * 256 + i * 16 + o];
        } else if (j < 144) {
            int o = j - 128;
            w = nb[i * 16 + o];
        } else {
            int o = j - 144;
            w = rt[i * 16 + o];
        }
        Wc[t] = w;
    }
    for (int t = threadIdx.x; t < ROW; t += blockDim.x)
        Bc[t] = (t >= 144) ? bs[t - 144] : 0.f;
    __syncthreads();

    const int total = NN * (ROW / 4);  // one thread per float4 of output
    for (int g = blockIdx.x * blockDim.x + threadIdx.x; g < total;
         g += gridDim.x * blockDim.x) {
        int n = g / (ROW / 4);
        int j4 = g % (ROW / 4);
        const float4* xr = (const float4*)(in + (size_t)n * 16);
        float4 x0 = xr[0], x1 = xr[1], x2 = xr[2], x3 = xr[3];
        float xv[16] = {x0.x, x0.y, x0.z, x0.w, x1.x, x1.y, x1.z, x1.w,
                        x2.x, x2.y, x2.z, x2.w, x3.x, x3.y, x3.z, x3.w};
        float4 acc = *(const float4*)&Bc[j4 * 4];
#pragma unroll
        for (int i = 0; i < 16; i++) {
            float4 w = *(const float4*)&Wc[i * ROW + j4 * 4];
            acc = f4fma(xv[i], w, acc);
        }
        *(float4*)&g_Text[(size_t)n * ROW + j4 * 4] = acc;
    }
}

// 4 cooperative lanes per edge; lane c owns output columns 4c..4c+3.
//   msg[c4..c4+3] = xb[src,c4..] + sum_d ea[e,d] * T[src,d,c4..]
// Lane-group loads from one src row touch one 64B chunk per d -> ~1 line per
// 8-edge warp instruction group instead of 32 (the round-2 bottleneck).
__global__ void __launch_bounds__(256)
edge_kernel(const void* __restrict__ ei_raw,
            const float* __restrict__ ea,
            int layer, int do_cnt) {
    int gt = blockIdx.x * blockDim.x + threadIdx.x;
    int e = gt >> 2;
    if (e >= EE) return;
    int c4 = (gt & 3) * 4;   // float column offset within the 16-wide output

    int src, dst;
    if (g_is64) {
        const long long* ei = (const long long*)ei_raw;
        src = (int)ei[e];
        dst = (int)ei[EE + e];
    } else {
        const int* ei = (const int*)ei_raw;
        src = ei[e];
        dst = ei[EE + e];
    }
    if ((unsigned)src >= NN || (unsigned)dst >= NN) return;

    // all 4 lanes of the group load the same ea row (L1 broadcast)
    const float4* eap = (const float4*)(ea + (size_t)e * 8);
    float4 a0 = eap[0], a1 = eap[1];

    const float* Tr = g_Text + (size_t)src * ROW + c4;
    float4 m = *(const float4*)(Tr + 128);   // xb slice
    m = f4fma(a0.x, *(const float4*)(Tr + 0 * 16), m);
    m = f4fma(a0.y, *(const float4*)(Tr + 1 * 16), m);
    m = f4fma(a0.z, *(const float4*)(Tr + 2 * 16), m);
    m = f4fma(a0.w, *(const float4*)(Tr + 3 * 16), m);
    m = f4fma(a1.x, *(const float4*)(Tr + 4 * 16), m);
    m = f4fma(a1.y, *(const float4*)(Tr + 5 * 16), m);
    m = f4fma(a1.z, *(const float4*)(Tr + 6 * 16), m);
    m = f4fma(a1.w, *(const float4*)(Tr + 7 * 16), m);

    float* dstp = (layer ? g_agg1 : g_agg0) + (size_t)dst * 16 + c4;
    red4(dstp, m);
    if (do_cnt && (gt & 3) == 0) atomicAdd(&g_cnt[dst], 1.0f);
}

// h[n,o] = relu(agg0[n,o]/max(cnt,1) + rootx0[n,o])
__global__ void relu_h_kernel() {
    int idx = blockIdx.x * blockDim.x + threadIdx.x;
    if (idx >= NN * 16) return;
    int n = idx >> 4, o = idx & 15;
    float c = fmaxf(g_cnt[n], 1.f);
    float v = g_agg0[idx] / c + g_Text[(size_t)n * ROW + 144 + o];
    g_h[idx] = fmaxf(v, 0.f);
}

// out[n] = sum_o relu(agg1[n,o]/max(cnt,1) + rootx1[n,o]) * head_w[o] + head_b
__global__ void head_kernel(const float* __restrict__ hw,
                            const float* __restrict__ hb,
                            float* __restrict__ out) {
    int n = blockIdx.x * blockDim.x + threadIdx.x;
    if (n >= NN) return;
    float inv = 1.f / fmaxf(g_cnt[n], 1.f);
    const float* ag = g_agg1 + (size_t)n * 16;
    const float* rx = g_Text + (size_t)n * ROW + 144;
    float s = hb[0];
#pragma unroll
    for (int o = 0; o < 16; o++) {
        float v = fmaxf(fmaf(ag[o], inv, rx[o]), 0.f);
        s = fmaf(v, hw[o], s);
    }
    out[n] = s;
}

// ---------------- launch ----------------
extern "C" void kernel_launch(void* const* d_in, const int* in_sizes, int n_in,
                              void* d_out, int out_size) {
    const float* x     = (const float*)d_in[0];
    const void*  ei    = d_in[1];
    const float* ea    = (const float*)d_in[2];
    const float* nn_w0 = (const float*)d_in[3];
    const float* nn_b0 = (const float*)d_in[4];
    const float* root0 = (const float*)d_in[5];
    const float* bias0 = (const float*)d_in[6];
    const float* nn_w1 = (const float*)d_in[7];
    const float* nn_b1 = (const float*)d_in[8];
    const float* root1 = (const float*)d_in[9];
    const float* bias1 = (const float*)d_in[10];
    const float* headw = (const float*)d_in[11];
    const float* headb = (const float*)d_in[12];
    float* out = (float*)d_out;

    const int TB = 256;
    const int EB = (EE * 4 + TB - 1) / TB;   // 4 lanes per edge

    detect_kernel<<<1, 1>>>(ei);
    zero_kernel<<<1024, TB>>>();
    node_prep_kernel<<<1184, TB>>>(x, nn_w0, nn_b0, root0, bias0);
    edge_kernel<<<EB, TB>>>(ei, ea, /*layer=*/0, /*do_cnt=*/1);
    relu_h_kernel<<<(NN * 16 + TB - 1) / TB, TB>>>();
    node_prep_kernel<<<1184, TB>>>(nullptr, nn_w1, nn_b1, root1, bias1);
    edge_kernel<<<EB, TB>>>(ei, ea, /*layer=*/1, /*do_cnt=*/0);
    head_kernel<<<(NN + TB - 1) / TB, TB>>>(headw, headb, out);
}

// round 6
// speedup vs baseline: 2.1261x; 1.0505x over previous
#include <cuda_runtime.h>

// Problem constants
#define NN   50000
#define EE   800000
#define ROW  160      // Text row stride in floats: [T 0..127 | xb 128..143 | rootx 144..159]
                      // 640 B/row = 5 x 128B lines; line k holds d=2k,2k+1 (k<4), line 4 = xb|rootx.

// ---------------- scratch (static device memory; no runtime allocation) ----------------
__device__ float g_Text[(size_t)NN * ROW];  // 32 MB, fits L2
__device__ float g_h[NN * 16];
__device__ float g_agg0[NN * 16];
__device__ float g_agg1[NN * 16];
__device__ float g_cnt[NN];
__device__ int   g_is64;   // 1 if edge_index is int64, 0 if int32

// ---------------- helpers ----------------
__device__ __forceinline__ float4 f4fma(float s, float4 a, float4 b) {
    b.x = fmaf(s, a.x, b.x);
    b.y = fmaf(s, a.y, b.y);
    b.z = fmaf(s, a.z, b.z);
    b.w = fmaf(s, a.w, b.w);
    return b;
}

// vectorized no-return atomic add (sm_90+, PTX ISA 8.1)
__device__ __forceinline__ void red4(float* p, float4 v) {
    asm volatile("red.global.add.v4.f32 [%0], {%1, %2, %3, %4};"
                 :: "l"(p), "f"(v.x), "f"(v.y), "f"(v.z), "f"(v.w)
                 : "memory");
}

// ---------------- kernels ----------------

// Probe edge_index dtype: int64 vs JAX-x64-disabled int32.
__global__ void detect_kernel(const void* ei) {
    const unsigned long long* p = (const unsigned long long*)ei;
    int ok = 1;
    for (int i = 0; i < 64; i++) {
        if (p[i] >= (unsigned long long)NN) { ok = 0; break; }
    }
    g_is64 = ok;
}

__global__ void zero_kernel() {
    int idx = blockIdx.x * blockDim.x + threadIdx.x;
    int stride = gridDim.x * blockDim.x;
    for (int i = idx; i < NN * 16; i += stride) {
        g_agg0[i] = 0.f;
        g_agg1[i] = 0.f;
    }
    for (int i = idx; i < NN; i += stride) g_cnt[i] = 0.f;
}

// Build Text[n, 0..159]:
//   j in [0,128):   T[n,d,o]    = sum_i in[n,i] * nn_w[d*256 + i*16 + o]   (d=j>>4, o=j&15)
//   j in [128,144): xb[n,o]     = sum_i in[n,i] * nn_b[i*16 + o]
//   j in [144,160): rootx[n,o]  = sum_i in[n,i] * root[i*16 + o] + bias[o]
__global__ void node_prep_kernel(const float* __restrict__ xin,   // nullptr -> use g_h
                                 const float* __restrict__ nw,
                                 const float* __restrict__ nb,
                                 const float* __restrict__ rt,
                                 const float* __restrict__ bs) {
    __shared__ float Wc[16 * ROW];
    __shared__ float Bc[ROW];
    const float* in = (xin != nullptr) ? xin : g_h;

    for (int t = threadIdx.x; t < 16 * ROW; t += blockDim.x) {
        int i = t / ROW, j = t % ROW;
        float w;
        if (j < 128) {
            int d = j >> 4, o = j & 15;
            w = nw[d * 256 + i * 16 + o];
        } else if (j < 144) {
            int o = j - 128;
            w = nb[i * 16 + o];
        } else {
            int o = j - 144;
            w = rt[i * 16 + o];
        }
        Wc[t] = w;
    }
    for (int t = threadIdx.x; t < ROW; t += blockDim.x)
        Bc[t] = (t >= 144) ? bs[t - 144] : 0.f;
    __syncthreads();

    const int total = NN * (ROW / 4);  // one thread per float4 of output
    for (int g = blockIdx.x * blockDim.x + threadIdx.x; g < total;
         g += gridDim.x * blockDim.x) {
        int n = g / (ROW / 4);
        int j4 = g % (ROW / 4);
        const float4* xr = (const float4*)(in + (size_t)n * 16);
        float4 x0 = xr[0], x1 = xr[1], x2 = xr[2], x3 = xr[3];
        float xv[16] = {x0.x, x0.y, x0.z, x0.w, x1.x, x1.y, x1.z, x1.w,
                        x2.x, x2.y, x2.z, x2.w, x3.x, x3.y, x3.z, x3.w};
        float4 acc = *(const float4*)&Bc[j4 * 4];
#pragma unroll
        for (int i = 0; i < 16; i++) {
            float4 w = *(const float4*)&Wc[i * ROW + j4 * 4];
            acc = f4fma(xv[i], w, acc);
        }
        *(float4*)&g_Text[(size_t)n * ROW + j4 * 4] = acc;
    }
}

// 8 cooperative lanes per edge. Lane l loads float4 at row + k*32 + l*4 for
// k=0..4 -> each load instruction covers one full 128B line per edge (the
// round-5 version paid 2 wavefronts per line). Lane's h=l>>2 selects even(0)/
// odd(1) d indices; lanes (l, l+4) hold all 8 d's of column group l&3 and are
// combined with one shfl_down(4). Line 4 gives xb to h=0 lanes for free.
__global__ void __launch_bounds__(256)
edge_kernel(const void* __restrict__ ei_raw,
            const float* __restrict__ ea,
            int layer, int do_cnt) {
    int gt = blockIdx.x * blockDim.x + threadIdx.x;
    int e = gt >> 3;
    if (e >= EE) return;           // grid is exact (EE*8 % 256 == 0); never taken
    int l = gt & 7;
    int h = l >> 2;                // 0: even d's + xb; 1: odd d's
    int cg = (l & 3) * 4;          // output column offset this lane-pair owns

    int src, dst;
    if (g_is64) {
        const long long* ei = (const long long*)ei_raw;
        src = (int)ei[e];
        dst = (int)ei[EE + e];
    } else {
        const int* ei = (const int*)ei_raw;
        src = ei[e];
        dst = ei[EE + e];
    }
    // Defensive without breaking warp convergence for the shuffles below.
    bool ok = ((unsigned)src < NN) && ((unsigned)dst < NN);
    if (!ok) src = 0;

    // all 8 lanes of the group load the same ea row (L1 broadcast)
    const float4* eap = (const float4*)(ea + (size_t)e * 8);
    float4 a0 = eap[0], a1 = eap[1];
    float w0 = h ? a0.y : a0.x;    // ea[0+h]
    float w1 = h ? a0.w : a0.z;    // ea[2+h]
    float w2 = h ? a1.y : a1.x;    // ea[4+h]
    float w3 = h ? a1.w : a1.z;    // ea[6+h]

    const float* Tr = g_Text + (size_t)src * ROW + l * 4;
    float4 t0 = *(const float4*)(Tr + 0);     // T[0+h][cg..]
    float4 t1 = *(const float4*)(Tr + 32);    // T[2+h][cg..]
    float4 t2 = *(const float4*)(Tr + 64);    // T[4+h][cg..]
    float4 t3 = *(const float4*)(Tr + 96);    // T[6+h][cg..]
    float4 t4 = *(const float4*)(Tr + 128);   // h=0: xb[cg..]; h=1: rootx (unused)

    float4 p = h ? make_float4(0.f, 0.f, 0.f, 0.f) : t4;
    p = f4fma(w0, t0, p);
    p = f4fma(w1, t1, p);
    p = f4fma(w2, t2, p);
    p = f4fma(w3, t3, p);

    // combine even/odd halves: lane l += lane l+4 (converged, full mask)
    p.x += __shfl_down_sync(0xffffffffu, p.x, 4);
    p.y += __shfl_down_sync(0xffffffffu, p.y, 4);
    p.z += __shfl_down_sync(0xffffffffu, p.z, 4);
    p.w += __shfl_down_sync(0xffffffffu, p.w, 4);

    if (h == 0 && ok) {
        float* dstp = (layer ? g_agg1 : g_agg0) + (size_t)dst * 16 + cg;
        red4(dstp, p);
        if (do_cnt && l == 0) atomicAdd(&g_cnt[dst], 1.0f);
    }
}

// h[n,o] = relu(agg0[n,o]/max(cnt,1) + rootx0[n,o])
__global__ void relu_h_kernel() {
    int idx = blockIdx.x * blockDim.x + threadIdx.x;
    if (idx >= NN * 16) return;
    int n = idx >> 4, o = idx & 15;
    float c = fmaxf(g_cnt[n], 1.f);
    float v = g_agg0[idx] / c + g_Text[(size_t)n * ROW + 144 + o];
    g_h[idx] = fmaxf(v, 0.f);
}

// out[n] = sum_o relu(agg1[n,o]/max(cnt,1) + rootx1[n,o]) * head_w[o] + head_b
__global__ void head_kernel(const float* __restrict__ hw,
                            const float* __restrict__ hb,
                            float* __restrict__ out) {
    int n = blockIdx.x * blockDim.x + threadIdx.x;
    if (n >= NN) return;
    float inv = 1.f / fmaxf(g_cnt[n], 1.f);
    const float* ag = g_agg1 + (size_t)n * 16;
    const float* rx = g_Text + (size_t)n * ROW + 144;
    float s = hb[0];
#pragma unroll
    for (int o = 0; o < 16; o++) {
        float v = fmaxf(fmaf(ag[o], inv, rx[o]), 0.f);
        s = fmaf(v, hw[o], s);
    }
    out[n] = s;
}

// ---------------- launch ----------------
extern "C" void kernel_launch(void* const* d_in, const int* in_sizes, int n_in,
                              void* d_out, int out_size) {
    const float* x     = (const float*)d_in[0];
    const void*  ei    = d_in[1];
    const float* ea    = (const float*)d_in[2];
    const float* nn_w0 = (const float*)d_in[3];
    const float* nn_b0 = (const float*)d_in[4];
    const float* root0 = (const float*)d_in[5];
    const float* bias0 = (const float*)d_in[6];
    const float* nn_w1 = (const float*)d_in[7];
    const float* nn_b1 = (const float*)d_in[8];
    const float* root1 = (const float*)d_in[9];
    const float* bias1 = (const float*)d_in[10];
    const float* headw = (const float*)d_in[11];
    const float* headb = (const float*)d_in[12];
    float* out = (float*)d_out;

    const int TB = 256;
    const int EB = (EE * 8 + TB - 1) / TB;   // 8 lanes per edge

    detect_kernel<<<1, 1>>>(ei);
    zero_kernel<<<1024, TB>>>();
    node_prep_kernel<<<1184, TB>>>(x, nn_w0, nn_b0, root0, bias0);
    edge_kernel<<<EB, TB>>>(ei, ea, /*layer=*/0, /*do_cnt=*/1);
    relu_h_kernel<<<(NN * 16 + TB - 1) / TB, TB>>>();
    node_prep_kernel<<<1184, TB>>>(nullptr, nn_w1, nn_b1, root1, bias1);
    edge_kernel<<<EB, TB>>>(ei, ea, /*layer=*/1, /*do_cnt=*/0);
    head_kernel<<<(NN + TB - 1) / TB, TB>>>(headw, headb, out);
}